// round 16
// baseline (speedup 1.0000x reference)
#include <cuda_runtime.h>

// Batched active-set (water-filling) projection — warp-per-row, threshold-set
// Newton with warm starts AND a fused prologue:
//   the s0 reduction pass simultaneously scans at the fixed warm-start
//   threshold T = -0.19, so the first phase-0 Newton update falls out of the
//   prologue — one full serial round removed.
// Newton (exact solve on the current threshold set) reaches each phase's
// unique fixed point finitely from any start; the start affects only scan
// count, never the converged set (validated at rel_err 1e-7 across rounds).
// All decision/output arithmetic is exact: float compares, 2^18 fixed-point
// REDUX.ADD sums, __fdividef water level.
//
// Phase 0: lower set {y < T}, T = -fill (fill monotone toward root).
// Phase 1: upper set {d = y-u > T} over the frozen complement; lower-clamps
// poisoned to -INF in yv. upper lives in shared memory. Warp-private loops.

#define NCOLS 1024
#define EPL 32
#define WARPS_PER_BLOCK 2
#define THREADS (WARPS_PER_BLOCK * 32)

#define SCALEF   262144.0f              // 2^18
#define INVSCALE (1.0f / 262144.0f)

__global__ __launch_bounds__(THREADS)
void proj_kernel(const float* __restrict__ y,
                 const float* __restrict__ upper,
                 float* __restrict__ out) {
    const int lane = threadIdx.x & 31;
    const int row  = blockIdx.x * WARPS_PER_BLOCK + (threadIdx.x >> 5);

    __shared__ float su[NCOLS];
    {
        const float4* u4 = reinterpret_cast<const float4*>(upper);
        float4*       s4 = reinterpret_cast<float4*>(su);
        #pragma unroll
        for (int k = 0; k < 4; k++)
            s4[threadIdx.x + THREADS * k] = u4[threadIdx.x + THREADS * k];
    }
    __syncthreads();   // one-time; warps independent afterwards

    const float NEG_INF = __int_as_float(0xff800000);

    float yv[EPL];
    {
        const float4* yrow = reinterpret_cast<const float4*>(y + (size_t)row * NCOLS);
        #pragma unroll
        for (int k = 0; k < 8; k++) {
            const float4 a = yrow[lane + 32 * k];
            yv[4*k+0]=a.x; yv[4*k+1]=a.y; yv[4*k+2]=a.z; yv[4*k+3]=a.w;
        }
    }

    // ---- fused prologue: s0 = sum(y) AND warm-start scan at T = -0.19 ----
    const float TW = -0.19f;
    float base0;
    int   prev;
    float T;            // current threshold = -fill
    {
        float a0=0.f,a1=0.f,a2=0.f,a3=0.f;          // total sum
        int   c0=0,c1=0,c2=0,c3=0;                  // warm count
        float d0=0.f,d1=0.f,d2=0.f,d3=0.f;          // warm lower-sum
        #pragma unroll
        for (int e = 0; e < EPL; e += 4) {
            a0 += yv[e+0]; a1 += yv[e+1]; a2 += yv[e+2]; a3 += yv[e+3];
            const bool p0 = yv[e+0] < TW, p1 = yv[e+1] < TW,
                       p2 = yv[e+2] < TW, p3 = yv[e+3] < TW;
            c0 += p0; c1 += p1; c2 += p2; c3 += p3;
            d0 += p0 ? yv[e+0] : 0.f; d1 += p1 ? yv[e+1] : 0.f;
            d2 += p2 ? yv[e+2] : 0.f; d3 += p3 ? yv[e+3] : 0.f;
        }
        const int s0i = __reduce_add_sync(0xffffffffu,
              (__float2int_rn(a0*SCALEF)+__float2int_rn(a1*SCALEF))
            + (__float2int_rn(a2*SCALEF)+__float2int_rn(a3*SCALEF)));
        const int cr  = __reduce_add_sync(0xffffffffu, (c0+c1)+(c2+c3));
        const int dr  = __reduce_add_sync(0xffffffffu,
              (__float2int_rn(d0*SCALEF)+__float2int_rn(d1*SCALEF))
            + (__float2int_rn(d2*SCALEF)+__float2int_rn(d3*SCALEF)));
        base0 = 512.0f - (float)s0i * INVSCALE;
        const float D = (float)dr * INVSCALE;
        prev = cr;
        T = -__fdividef(base0 + D, fmaxf(1024.0f - (float)cr, 1.0f));
    }

    int   it = 1;                 // prologue counted as round 1
    float maskT0 = TW;
    bool  p0conv = false;
    float cntF = 0.0f, dsF = 0.0f;

    // ---- phase 0: lower clamps (threshold scan on y) ----
    {
        for (;;) {
            ++it;
            int   c0=0,c1=0,c2=0,c3=0;
            float d0=0.f,d1=0.f,d2=0.f,d3=0.f;
            #pragma unroll
            for (int e = 0; e < EPL; e += 4) {
                const bool p0 = yv[e+0] < T, p1 = yv[e+1] < T,
                           p2 = yv[e+2] < T, p3 = yv[e+3] < T;
                c0 += p0; c1 += p1; c2 += p2; c3 += p3;
                d0 += p0 ? yv[e+0] : 0.f; d1 += p1 ? yv[e+1] : 0.f;
                d2 += p2 ? yv[e+2] : 0.f; d3 += p3 ? yv[e+3] : 0.f;
            }
            const int cr = __reduce_add_sync(0xffffffffu, (c0+c1)+(c2+c3));
            const int dr = __reduce_add_sync(0xffffffffu,
                  (__float2int_rn(d0*SCALEF)+__float2int_rn(d1*SCALEF))
                + (__float2int_rn(d2*SCALEF)+__float2int_rn(d3*SCALEF)));
            const float D = (float)dr * INVSCALE;
            maskT0 = T; cntF = (float)cr; dsF = D;
            if (cr == prev) { p0conv = true; break; }   // set stable
            prev = cr;
            T = -__fdividef(base0 + D, fmaxf(1024.0f - (float)cr, 1.0f));
            if (it >= 40) break;                         // safety cap
        }
    }

    float4* orow = reinterpret_cast<float4*>(out + (size_t)row * NCOLS);
    const float4* su4 = reinterpret_cast<const float4*>(su);

    if (p0conv) {
        // phase transition: yv <- d = y-u (free) / -INF (lower-clamped)
        #pragma unroll
        for (int k = 0; k < 8; k++) {
            const float4 u4 = su4[lane + 32 * k];
            const float uu[4] = {u4.x, u4.y, u4.z, u4.w};
            #pragma unroll
            for (int j = 0; j < 4; j++) {
                const int e = 4 * k + j;
                yv[e] = (yv[e] < maskT0) ? NEG_INF : (yv[e] - uu[j]);
            }
        }
        const float base1 = base0 + dsF;
        const float n1    = 1024.0f - cntF;

        // phase-1 warm start: fill rises in phase 1 (T falls)
        T = maskT0 - 0.10f;

        // ---- phase 1: upper clamps (threshold scan on d) ----
        float maskT1 = 0.0f;
        float fill1;
        {
            int prev1 = -1;
            for (;;) {
                ++it;
                int   c0=0,c1=0,c2=0,c3=0;
                float d0=0.f,d1=0.f,d2=0.f,d3=0.f;
                #pragma unroll
                for (int e = 0; e < EPL; e += 4) {
                    const bool p0 = yv[e+0] > T, p1 = yv[e+1] > T,
                               p2 = yv[e+2] > T, p3 = yv[e+3] > T;
                    c0 += p0; c1 += p1; c2 += p2; c3 += p3;
                    d0 += p0 ? yv[e+0] : 0.f; d1 += p1 ? yv[e+1] : 0.f;
                    d2 += p2 ? yv[e+2] : 0.f; d3 += p3 ? yv[e+3] : 0.f;
                }
                const int cr = __reduce_add_sync(0xffffffffu, (c0+c1)+(c2+c3));
                const int ar = __reduce_add_sync(0xffffffffu,
                      (__float2int_rn(d0*SCALEF)+__float2int_rn(d1*SCALEF))
                    + (__float2int_rn(d2*SCALEF)+__float2int_rn(d3*SCALEF)));
                const float A = (float)ar * INVSCALE;
                maskT1 = T;
                fill1 = __fdividef(base1 + A, fmaxf(n1 - (float)cr, 1.0f));
                if (cr == prev1) break;
                prev1 = cr;
                T = -fill1;
                if (it >= 72) break;
            }
        }
        // note: at convergence fill1 == -maskT1 (same set); use -maskT1 for
        // exact consistency with the set tests
        fill1 = -maskT1;

        // epilogue: yv holds d. lower (-INF) -> 0; upper (d > T1) -> u;
        // free -> y + fill = d + u + fill
        #pragma unroll
        for (int k = 0; k < 8; k++) {
            const float4 u4 = su4[lane + 32 * k];
            const float uu[4] = {u4.x, u4.y, u4.z, u4.w};
            float o4[4];
            #pragma unroll
            for (int j = 0; j < 4; j++) {
                const int e = 4 * k + j;
                const float d = yv[e];
                o4[j] = (d == NEG_INF) ? 0.0f
                      : ((d > maskT1) ? uu[j] : d + uu[j] + fill1);
            }
            float4 v; v.x=o4[0]; v.y=o4[1]; v.z=o4[2]; v.w=o4[3];
            orow[lane + 32 * k] = v;
        }
    } else {
        // safety path (cap hit in phase 0)
        const float fill = -maskT0;
        #pragma unroll
        for (int k = 0; k < 8; k++) {
            float o4[4];
            #pragma unroll
            for (int j = 0; j < 4; j++) {
                const int e = 4 * k + j;
                o4[j] = (yv[e] < maskT0) ? 0.0f : yv[e] + fill;
            }
            float4 v; v.x=o4[0]; v.y=o4[1]; v.z=o4[2]; v.w=o4[3];
            orow[lane + 32 * k] = v;
        }
    }
}

extern "C" void kernel_launch(void* const* d_in, const int* in_sizes, int n_in,
                              void* d_out, int out_size) {
    const float* y     = (const float*)d_in[0];
    const float* upper = (const float*)d_in[1];
    float*       out   = (float*)d_out;
    const int rows   = in_sizes[0] / NCOLS;                      // 2048
    const int blocks = (rows + WARPS_PER_BLOCK - 1) / WARPS_PER_BLOCK;
    proj_kernel<<<blocks, THREADS>>>(y, upper, out);
}